// round 4
// baseline (speedup 1.0000x reference)
#include <cuda_runtime.h>
#include <cuda_bf16.h>
#include <math.h>

// encoded: (8, 64, 256, 256) f32, masks: (8,1,256,256) i32 (0..32)
// W1: (128,32), b1: (32,), W2: (32,4), b2: (4,)
// out: vectors (8,32,64) ++ connections (8,4,32,32)

#define BATCH 8
#define FDIM 64
#define HW 65536
#define SEGS 33
#define NOBJ 32

// per-batch completion counters (self-resetting each invocation)
__device__ int g_cnt[BATCH];

// Epilogue shared-memory overlay (reuses the accumulator buffer)
struct EpiShared {
    float sW1[128 * 32];   // 16 KB
    float sV[32][64];      // 8 KB
    float sA[32][SEGS];
    float sB[32][SEGS];
    float sW2[128];
    float sb1[32];
    float sb2[4];
};

// ---------------------------------------------------------------------------
// Fused kernel: 256 blocks x 256 threads.
// Block bf: b = bf>>5, f-planes f0 = bf&31 and f0+32.
// Segment-max with conflict-free float2 smem accumulators, then the last
// block per batch runs that batch's pair-MLP epilogue.
// ---------------------------------------------------------------------------
__global__ __launch_bounds__(256) void fused_kernel(
    const float* __restrict__ enc, const int* __restrict__ masks,
    const float* __restrict__ W1, const float* __restrict__ b1,
    const float* __restrict__ W2, const float* __restrict__ b2,
    float* __restrict__ vec_out, float* __restrict__ conn)
{
    extern __shared__ char smem_raw[];
    float2* acc2 = (float2*)smem_raw;            // SEGS*256 float2 = 67584 B

    const int bf = blockIdx.x;                   // 0..255
    const int b  = bf >> 5;
    const int f0 = bf & 31;

    const int t = threadIdx.x;
    const float NEG_INF = __int_as_float(0xff800000);
#pragma unroll
    for (int s = 0; s < SEGS; s++) acc2[s * 256 + t] = make_float2(NEG_INF, NEG_INF);

    const float4* p0 = (const float4*)(enc + ((size_t)b * FDIM + f0) * HW);
    const float4* p1 = (const float4*)(enc + ((size_t)b * FDIM + f0 + 32) * HW);
    const int4*   m4 = (const int4*)(masks + (size_t)b * HW);

    float2* ac = acc2 + t;

#pragma unroll 4
    for (int i = 0; i < 64; i++) {
        int idx = i * 256 + t;
        float4 v0 = p0[idx];
        float4 v1 = p1[idx];
        int4   m  = m4[idx];
        float2* px = ac + m.x * 256;
        float2* py = ac + m.y * 256;
        float2* pz = ac + m.z * 256;
        float2* pw = ac + m.w * 256;
        float2 axv = *px; axv.x = fmaxf(axv.x, v0.x); axv.y = fmaxf(axv.y, v1.x); *px = axv;
        float2 ayv = *py; ayv.x = fmaxf(ayv.x, v0.y); ayv.y = fmaxf(ayv.y, v1.y); *py = ayv;
        float2 azv = *pz; azv.x = fmaxf(azv.x, v0.z); azv.y = fmaxf(azv.y, v1.z); *pz = azv;
        float2 awv = *pw; awv.x = fmaxf(awv.x, v0.w); awv.y = fmaxf(awv.y, v1.w); *pw = awv;
    }

    __syncthreads();

    // Reduce 256 columns per segment: 8 threads per segment, lane-staggered.
    {
        const int sidx = t >> 3;                 // segment sidx+1
        const int k    = t & 7;
        const float2* base = acc2 + (sidx + 1) * 256 + k * 32;
        float mx = NEG_INF, my = NEG_INF;
#pragma unroll
        for (int i = 0; i < 32; i++) {
            int j = (i + t) & 31;
            float2 v = base[j];
            mx = fmaxf(mx, v.x);
            my = fmaxf(my, v.y);
        }
        mx = fmaxf(mx, __shfl_down_sync(0xffffffffu, mx, 4, 8));
        mx = fmaxf(mx, __shfl_down_sync(0xffffffffu, mx, 2, 8));
        mx = fmaxf(mx, __shfl_down_sync(0xffffffffu, mx, 1, 8));
        my = fmaxf(my, __shfl_down_sync(0xffffffffu, my, 4, 8));
        my = fmaxf(my, __shfl_down_sync(0xffffffffu, my, 2, 8));
        my = fmaxf(my, __shfl_down_sync(0xffffffffu, my, 1, 8));
        if (k == 0) {
            float* vrow = vec_out + ((size_t)b * NOBJ + sidx) * FDIM;
            vrow[f0]      = mx;
            vrow[f0 + 32] = my;
        }
    }

    // ---- completion protocol: last block of batch b runs the MLP epilogue ----
    __threadfence();                 // make this thread's STGs visible
    __syncthreads();                 // all threads' stores are now fenced

    __shared__ int is_last;
    if (t == 0) {
        int rank = atomicAdd(&g_cnt[b], 1);
        is_last = (rank == NOBJ - 1) ? 1 : 0;    // 32 blocks per batch
    }
    __syncthreads();
    if (!is_last) return;

    __threadfence();                 // acquire side
    EpiShared* es = (EpiShared*)smem_raw;        // reuse accumulator smem
    // (safe: all threads passed the __syncthreads above; acc2 is dead)

    for (int i = t; i < 128 * 32; i += 256) es->sW1[i] = W1[i];
    for (int i = t; i < 32 * 64; i += 256)
        es->sV[i >> 6][i & 63] = __ldcg(vec_out + (size_t)b * 2048 + i);  // bypass L1
    if (t < 128) es->sW2[t] = W2[t];
    if (t < 32)  es->sb1[t] = b1[t];
    if (t < 4)   es->sb2[t] = b2[t];
    __syncthreads();

    // Phase A: sA = V @ W1[:64] + b1 ; sB = V @ W1[64:]
    for (int idx = t; idx < 1024; idx += 256) {
        const int i = idx >> 5;                  // warp-uniform
        const int k = idx & 31;                  // lane
        float accA = es->sb1[k];
        float accB = 0.f;
#pragma unroll 8
        for (int d = 0; d < 64; d++) {
            float v = es->sV[i][d];              // broadcast
            accA += v * es->sW1[d * 32 + k];
            accB += v * es->sW1[(64 + d) * 32 + k];
        }
        es->sA[i][k] = accA;
        es->sB[i][k] = accB;
    }
    __syncthreads();

    // Phase B: connections[b,c,j,i] = sigmoid((sA[i]+sB[j]) . W2[:,c] + b2[c])
    for (int idx = t; idx < 1024; idx += 256) {
        const int i = idx >> 5;                  // warp-uniform
        const int j = idx & 31;                  // lane
        float o0 = es->sb2[0], o1 = es->sb2[1], o2 = es->sb2[2], o3 = es->sb2[3];
#pragma unroll
        for (int k = 0; k < 32; k++) {
            float h = es->sA[i][k] + es->sB[j][k];
            o0 += h * es->sW2[k * 4 + 0];
            o1 += h * es->sW2[k * 4 + 1];
            o2 += h * es->sW2[k * 4 + 2];
            o3 += h * es->sW2[k * 4 + 3];
        }
        float* cb = conn + (size_t)b * 4096 + j * 32 + i;
        cb[0]    = 1.f / (1.f + expf(-o0));
        cb[1024] = 1.f / (1.f + expf(-o1));
        cb[2048] = 1.f / (1.f + expf(-o2));
        cb[3072] = 1.f / (1.f + expf(-o3));
    }

    // reset counter for next invocation (kernel-end ordering protects replays)
    if (t == 0) atomicExch(&g_cnt[b], 0);
}

// ---------------------------------------------------------------------------
extern "C" void kernel_launch(void* const* d_in, const int* in_sizes, int n_in,
                              void* d_out, int out_size)
{
    const float* enc   = (const float*)d_in[0];
    const int*   masks = (const int*)  d_in[1];
    const float* W1    = (const float*)d_in[2];
    const float* b1    = (const float*)d_in[3];
    const float* W2    = (const float*)d_in[4];
    const float* b2    = (const float*)d_in[5];

    float* out_f = (float*)d_out;
    float* vectors = out_f;                      // 8*32*64
    float* conn    = out_f + BATCH * NOBJ * FDIM;

    static bool attr_done = false;
    if (!attr_done) {
        cudaFuncSetAttribute(fused_kernel,
                             cudaFuncAttributeMaxDynamicSharedMemorySize,
                             SEGS * 256 * (int)sizeof(float2));
        attr_done = true;
    }

    fused_kernel<<<BATCH * 32, 256, SEGS * 256 * sizeof(float2)>>>(
        enc, masks, W1, b1, W2, b2, vectors, conn);
}

// round 5
// speedup vs baseline: 1.3058x; 1.3058x over previous
#include <cuda_runtime.h>
#include <cuda_bf16.h>
#include <math.h>

// encoded: (8, 64, 256, 256) f32, masks: (8,1,256,256) i32 (0..32)
// W1: (128,32), b1: (32,), W2: (32,4), b2: (4,)
// out: vectors (8,32,64) ++ connections (8,4,32,32)

#define BATCH 8
#define FDIM 64
#define HW 65536
#define SEGS 33
#define NOBJ 32

// ---------------------------------------------------------------------------
// K1: segment max. 256 blocks x 256 threads, 2 f-planes per block.
// Reads masks directly as int4 (L2 absorbs the 64x re-read).
// __launch_bounds__(256, 3): cap regs so 3 blocks/SM (smem allows exactly 3)
// -> all 256 blocks resident in one wave, 24 warps/SM of latency hiding.
// ---------------------------------------------------------------------------
__global__ __launch_bounds__(256, 3) void segmax_kernel(
    const float* __restrict__ enc, const int* __restrict__ masks,
    float* __restrict__ vec_out)
{
    extern __shared__ float2 acc2[];            // SEGS*256 float2 = 67584 B

    const int bf = blockIdx.x;                  // 0..255
    const int b  = bf >> 5;
    const int f0 = bf & 31;                     // planes f0, f0+32

    const int t = threadIdx.x;
    const float NEG_INF = __int_as_float(0xff800000);
#pragma unroll
    for (int s = 0; s < SEGS; s++) acc2[s * 256 + t] = make_float2(NEG_INF, NEG_INF);
    // each thread touches only its own column t -> no sync needed

    const float4* p0 = (const float4*)(enc + ((size_t)b * FDIM + f0) * HW);
    const float4* p1 = (const float4*)(enc + ((size_t)b * FDIM + f0 + 32) * HW);
    const int4*   m4 = (const int4*)(masks + (size_t)b * HW);

    float2* ac = acc2 + t;

#pragma unroll 4
    for (int i = 0; i < 64; i++) {
        int idx = i * 256 + t;                  // coalesced
        float4 v0 = p0[idx];
        float4 v1 = p1[idx];
        int4   m  = m4[idx];
        float2* px = ac + m.x * 256;
        float2* py = ac + m.y * 256;
        float2* pz = ac + m.z * 256;
        float2* pw = ac + m.w * 256;
        float2 a0 = *px; a0.x = fmaxf(a0.x, v0.x); a0.y = fmaxf(a0.y, v1.x); *px = a0;
        float2 a1 = *py; a1.x = fmaxf(a1.x, v0.y); a1.y = fmaxf(a1.y, v1.y); *py = a1;
        float2 a2 = *pz; a2.x = fmaxf(a2.x, v0.z); a2.y = fmaxf(a2.y, v1.z); *pz = a2;
        float2 a3 = *pw; a3.x = fmaxf(a3.x, v0.w); a3.y = fmaxf(a3.y, v1.w); *pw = a3;
    }

    __syncthreads();

    // Reduce 256 columns per segment: 8 threads/segment, lane-staggered banks.
    {
        const int sidx = t >> 3;                // segment sidx+1
        const int k    = t & 7;
        const float2* base = acc2 + (sidx + 1) * 256 + k * 32;
        float mx = NEG_INF, my = NEG_INF;
#pragma unroll
        for (int i = 0; i < 32; i++) {
            int j = (i + t) & 31;               // bank distinct per lane
            float2 v = base[j];
            mx = fmaxf(mx, v.x);
            my = fmaxf(my, v.y);
        }
        mx = fmaxf(mx, __shfl_down_sync(0xffffffffu, mx, 4, 8));
        mx = fmaxf(mx, __shfl_down_sync(0xffffffffu, mx, 2, 8));
        mx = fmaxf(mx, __shfl_down_sync(0xffffffffu, mx, 1, 8));
        my = fmaxf(my, __shfl_down_sync(0xffffffffu, my, 4, 8));
        my = fmaxf(my, __shfl_down_sync(0xffffffffu, my, 2, 8));
        my = fmaxf(my, __shfl_down_sync(0xffffffffu, my, 1, 8));
        if (k == 0) {
            float* vrow = vec_out + ((size_t)b * NOBJ + sidx) * FDIM;
            vrow[f0]      = mx;
            vrow[f0 + 32] = my;
        }
    }
}

// ---------------------------------------------------------------------------
// K2: pair MLP (algebraically reduced).
//   h[b,i,j,k] = (V W1_top)[i,k] + (V W1_bot)[j,k] + b1[k]
//   connections[b,c,j,i] = sigmoid(h . W2[:,c] + b2[c])
// One block per batch, 1024 threads.
// ---------------------------------------------------------------------------
__global__ __launch_bounds__(1024) void pair_mlp_kernel(
    const float* __restrict__ vec, const float* __restrict__ W1,
    const float* __restrict__ b1, const float* __restrict__ W2,
    const float* __restrict__ b2, float* __restrict__ conn)
{
    const int b = blockIdx.x;
    const int t = threadIdx.x;

    __shared__ float sW1[128 * 32];
    __shared__ float sV[32][64];
    __shared__ float sA[32][SEGS];
    __shared__ float sB[32][SEGS];
    __shared__ float sW2[128];
    __shared__ float sb2[4];

    for (int i = t; i < 128 * 32; i += 1024) sW1[i] = W1[i];
    for (int i = t; i < 32 * 64; i += 1024)  sV[i >> 6][i & 63] = vec[(size_t)b * 2048 + i];
    if (t < 128) sW2[t] = W2[t];
    if (t < 4)   sb2[t] = b2[t];
    __syncthreads();

    {
        const int i = t >> 5;
        const int k = t & 31;
        float accA = b1[k];
        float accB = 0.f;
#pragma unroll 8
        for (int d = 0; d < 64; d++) {
            float v = sV[i][d];                 // warp broadcast
            accA += v * sW1[d * 32 + k];
            accB += v * sW1[(64 + d) * 32 + k];
        }
        sA[i][k] = accA;
        sB[i][k] = accB;
    }
    __syncthreads();

    {
        const int i = t >> 5;
        const int j = t & 31;
        float o0 = sb2[0], o1 = sb2[1], o2 = sb2[2], o3 = sb2[3];
#pragma unroll
        for (int k = 0; k < 32; k++) {
            float h = sA[i][k] + sB[j][k];
            o0 += h * sW2[k * 4 + 0];
            o1 += h * sW2[k * 4 + 1];
            o2 += h * sW2[k * 4 + 2];
            o3 += h * sW2[k * 4 + 3];
        }
        float* cb = conn + (size_t)b * 4096 + j * 32 + i;
        cb[0]    = 1.f / (1.f + expf(-o0));
        cb[1024] = 1.f / (1.f + expf(-o1));
        cb[2048] = 1.f / (1.f + expf(-o2));
        cb[3072] = 1.f / (1.f + expf(-o3));
    }
}

// ---------------------------------------------------------------------------
extern "C" void kernel_launch(void* const* d_in, const int* in_sizes, int n_in,
                              void* d_out, int out_size)
{
    const float* enc   = (const float*)d_in[0];
    const int*   masks = (const int*)  d_in[1];
    const float* W1    = (const float*)d_in[2];
    const float* b1    = (const float*)d_in[3];
    const float* W2    = (const float*)d_in[4];
    const float* b2    = (const float*)d_in[5];

    float* out_f = (float*)d_out;
    float* vectors = out_f;
    float* conn    = out_f + BATCH * NOBJ * FDIM;

    static bool attr_done = false;
    if (!attr_done) {
        cudaFuncSetAttribute(segmax_kernel,
                             cudaFuncAttributeMaxDynamicSharedMemorySize,
                             SEGS * 256 * (int)sizeof(float2));
        attr_done = true;
    }

    segmax_kernel<<<BATCH * 32, 256, SEGS * 256 * sizeof(float2)>>>(enc, masks, vectors);
    pair_mlp_kernel<<<BATCH, 1024>>>(vectors, W1, b1, W2, b2, conn);
}

// round 6
// speedup vs baseline: 1.4757x; 1.1301x over previous
#include <cuda_runtime.h>
#include <cuda_bf16.h>
#include <math.h>

// encoded: (8, 64, 256, 256) f32, masks: (8,1,256,256) i32 (0..32)
// W1: (128,32), b1: (32,), W2: (32,4), b2: (4,)
// out: vectors (8,32,64) ++ connections (8,4,32,32)

#define BATCH 8
#define FDIM 64
#define HW 65536
#define SEGS 33
#define NOBJ 32

__device__ unsigned char g_mask8[BATCH * HW];

// ---------------------------------------------------------------------------
// K0: pack int32 masks -> uint8. 1 int4 -> 1 uint per thread; 131072 threads.
// ---------------------------------------------------------------------------
__global__ __launch_bounds__(256) void pack_mask_kernel(const int* __restrict__ masks)
{
    int i = blockIdx.x * blockDim.x + threadIdx.x;
    int4 v = ((const int4*)masks)[i];
    unsigned int o = (v.x & 0xff) | ((v.y & 0xff) << 8) |
                     ((v.z & 0xff) << 16) | (v.w << 24);
    ((unsigned int*)g_mask8)[i] = o;
}

// ---------------------------------------------------------------------------
// K1: segment max (exact R3 configuration — best measured: ~29.5us).
// 256 blocks x 256 threads, 2 f-planes per block, packed uchar4 masks,
// conflict-free float2 accumulators acc2[s*256 + t].
// ---------------------------------------------------------------------------
__global__ __launch_bounds__(256) void segmax_kernel(
    const float* __restrict__ enc, float* __restrict__ vec_out)
{
    extern __shared__ float2 acc2[];            // SEGS*256 float2 = 67584 B

    const int bf = blockIdx.x;                  // 0..255
    const int b  = bf >> 5;
    const int f0 = bf & 31;                     // planes f0, f0+32

    const int t = threadIdx.x;
    const float NEG_INF = __int_as_float(0xff800000);
#pragma unroll
    for (int s = 0; s < SEGS; s++) acc2[s * 256 + t] = make_float2(NEG_INF, NEG_INF);

    const float4* p0 = (const float4*)(enc + ((size_t)b * FDIM + f0) * HW);
    const float4* p1 = (const float4*)(enc + ((size_t)b * FDIM + f0 + 32) * HW);
    const uchar4* m4 = (const uchar4*)(g_mask8 + (size_t)b * HW);

    float2* ac = acc2 + t;

#pragma unroll 4
    for (int i = 0; i < 64; i++) {
        int idx = i * 256 + t;
        float4 v0 = p0[idx];
        float4 v1 = p1[idx];
        uchar4 m  = m4[idx];
        float2* px = ac + (int)m.x * 256;
        float2* py = ac + (int)m.y * 256;
        float2* pz = ac + (int)m.z * 256;
        float2* pw = ac + (int)m.w * 256;
        float2 a0 = *px; a0.x = fmaxf(a0.x, v0.x); a0.y = fmaxf(a0.y, v1.x); *px = a0;
        float2 a1 = *py; a1.x = fmaxf(a1.x, v0.y); a1.y = fmaxf(a1.y, v1.y); *py = a1;
        float2 a2 = *pz; a2.x = fmaxf(a2.x, v0.z); a2.y = fmaxf(a2.y, v1.z); *pz = a2;
        float2 a3 = *pw; a3.x = fmaxf(a3.x, v0.w); a3.y = fmaxf(a3.y, v1.w); *pw = a3;
    }

    __syncthreads();

    {
        const int sidx = t >> 3;                // segment sidx+1
        const int k    = t & 7;
        const float2* base = acc2 + (sidx + 1) * 256 + k * 32;
        float mx = NEG_INF, my = NEG_INF;
#pragma unroll
        for (int i = 0; i < 32; i++) {
            int j = (i + t) & 31;
            float2 v = base[j];
            mx = fmaxf(mx, v.x);
            my = fmaxf(my, v.y);
        }
        mx = fmaxf(mx, __shfl_down_sync(0xffffffffu, mx, 4, 8));
        mx = fmaxf(mx, __shfl_down_sync(0xffffffffu, mx, 2, 8));
        mx = fmaxf(mx, __shfl_down_sync(0xffffffffu, mx, 1, 8));
        my = fmaxf(my, __shfl_down_sync(0xffffffffu, my, 4, 8));
        my = fmaxf(my, __shfl_down_sync(0xffffffffu, my, 2, 8));
        my = fmaxf(my, __shfl_down_sync(0xffffffffu, my, 1, 8));
        if (k == 0) {
            float* vrow = vec_out + ((size_t)b * NOBJ + sidx) * FDIM;
            vrow[f0]      = mx;
            vrow[f0 + 32] = my;
        }
    }
}

// ---------------------------------------------------------------------------
// K2: pair MLP — 32 blocks (8 batches x 4 i-tiles), 256 threads.
//   A[i,k] = (V W1_top)[i,k] + b1[k]   (8 i's per block, 1 entry/thread)
//   B[j,k] = (V W1_bot)[j,k]           (all 32 j's, 4 entries/thread, redundant)
//   connections[b,c,j,i] = sigmoid((A[i]+B[j]) . W2[:,c] + b2[c])
// ---------------------------------------------------------------------------
__global__ __launch_bounds__(256) void pair_mlp_kernel(
    const float* __restrict__ vec, const float* __restrict__ W1,
    const float* __restrict__ b1, const float* __restrict__ W2,
    const float* __restrict__ b2, float* __restrict__ conn)
{
    const int b    = blockIdx.x >> 2;
    const int tile = blockIdx.x & 3;        // i in [tile*8, tile*8+8)
    const int t    = threadIdx.x;

    __shared__ float sW1[128 * 32];         // 16 KB
    __shared__ float sV[32][64];            // 8 KB
    __shared__ float sA[8][SEGS];
    __shared__ float sB[32][SEGS];
    __shared__ float sW2[128];
    __shared__ float sb1[32];
    __shared__ float sb2[4];

    // coalesced float4 weight/vector loads
    {
        const float4* w4 = (const float4*)W1;
#pragma unroll
        for (int r = 0; r < 4; r++) ((float4*)sW1)[r * 256 + t] = w4[r * 256 + t];
        const float4* v4 = (const float4*)(vec + (size_t)b * 2048);
#pragma unroll
        for (int r = 0; r < 2; r++) {
            int idx = r * 256 + t;          // 512 float4 = 2048 floats
            ((float4*)sV)[idx] = v4[idx];
        }
        if (t < 128) sW2[t] = W2[t];
        if (t < 32)  sb1[t] = b1[t];
        if (t < 4)   sb2[t] = b2[t];
    }
    __syncthreads();

    // Phase A: this tile's A rows (1 entry/thread) + full B (4 entries/thread)
    {
        const int il = t >> 5;              // 0..7 (warp-uniform)
        const int k  = t & 31;              // lane
        const int i  = tile * 8 + il;
        float a = sb1[k];
#pragma unroll 8
        for (int d = 0; d < 64; d++)
            a += sV[i][d] * sW1[d * 32 + k];    // broadcast + conflict-free
        sA[il][k] = a;

#pragma unroll
        for (int r = 0; r < 4; r++) {
            const int j = r * 8 + il;       // warp-uniform
            float bb = 0.f;
#pragma unroll 8
            for (int d = 0; d < 64; d++)
                bb += sV[j][d] * sW1[(64 + d) * 32 + k];
            sB[j][k] = bb;
        }
    }
    __syncthreads();

    // Phase B: 8 i x 32 j pairs, one per thread
    {
        const int il = t >> 5;              // warp-uniform
        const int j  = t & 31;              // lane
        const int i  = tile * 8 + il;
        float o0 = sb2[0], o1 = sb2[1], o2 = sb2[2], o3 = sb2[3];
#pragma unroll
        for (int k = 0; k < 32; k++) {
            float h = sA[il][k] + sB[j][k];     // broadcast + conflict-free
            o0 += h * sW2[k * 4 + 0];
            o1 += h * sW2[k * 4 + 1];
            o2 += h * sW2[k * 4 + 2];
            o3 += h * sW2[k * 4 + 3];
        }
        float* cb = conn + (size_t)b * 4096 + j * 32 + i;
        cb[0]    = 1.f / (1.f + __expf(-o0));
        cb[1024] = 1.f / (1.f + __expf(-o1));
        cb[2048] = 1.f / (1.f + __expf(-o2));
        cb[3072] = 1.f / (1.f + __expf(-o3));
    }
}

// ---------------------------------------------------------------------------
extern "C" void kernel_launch(void* const* d_in, const int* in_sizes, int n_in,
                              void* d_out, int out_size)
{
    const float* enc   = (const float*)d_in[0];
    const int*   masks = (const int*)  d_in[1];
    const float* W1    = (const float*)d_in[2];
    const float* b1    = (const float*)d_in[3];
    const float* W2    = (const float*)d_in[4];
    const float* b2    = (const float*)d_in[5];

    float* out_f = (float*)d_out;
    float* vectors = out_f;
    float* conn    = out_f + BATCH * NOBJ * FDIM;

    static bool attr_done = false;
    if (!attr_done) {
        cudaFuncSetAttribute(segmax_kernel,
                             cudaFuncAttributeMaxDynamicSharedMemorySize,
                             SEGS * 256 * (int)sizeof(float2));
        attr_done = true;
    }

    pack_mask_kernel<<<512, 256>>>(masks);
    segmax_kernel<<<BATCH * 32, 256, SEGS * 256 * sizeof(float2)>>>(enc, vectors);
    pair_mlp_kernel<<<BATCH * 4, 256>>>(vectors, W1, b1, W2, b2, conn);
}